// round 14
// baseline (speedup 1.0000x reference)
#include <cuda_runtime.h>

#define PDIM     512
#define TPQ      64
#define TPP      64
#define CH       16
#define NTHREADS 256
#define NITEMS   8192     // 128 batch-pairs * 64 tiles
#define NCTAS    888      // 148 SMs * 6 resident CTAs

__device__ __forceinline__ float clamp01f(float v) {
    return fminf(fmaxf(v, 0.0f), 1.0f);
}

__device__ __forceinline__ float h_of(int img, float X, float Y, float fq) {
    return (img == 0) ? clamp01f(fminf(fq + 1.0f - X, Y - fq))
                      : clamp01f(fq + 1.0f - X);
}
__device__ __forceinline__ float u_of(int img, float X, float Y, float fp) {
    return (img == 0) ? clamp01f(fminf(512.0f - fp - Y, X + 1.0f + fp))
                      : clamp01f(Y - 511.0f + fp);
}

__device__ __forceinline__ void stcs4(float* p, float4 v) {
    asm volatile("st.global.cs.v4.f32 [%0], {%1,%2,%3,%4};"
                 :: "l"(p), "f"(v.x), "f"(v.y), "f"(v.z), "f"(v.w) : "memory");
}

__global__ __launch_bounds__(NTHREADS, 6)
void hilbert_raster_kernel(const float* __restrict__ iv00,
                           const float* __restrict__ iv01,
                           float* __restrict__ out)
{
    __shared__ float Xs[128], Ys[128];          // two batches of 64 factors
    __shared__ float Arow[TPP], Bcol[TPQ];
    __shared__ unsigned char listA[64], listB[64], listC[64];
    __shared__ int wCnt[2][4];
    __shared__ float Us[CH][TPP], Hs[CH][TPQ];

    const int t  = threadIdx.x;
    const int tx = t & 15;   // q: 16 groups * 4 cols = 64
    const int ty = t >> 4;   // p: 16 groups * 4 rows = 64
    const float INV_SIDE = 325.94932345220167f;  // 1024/pi

    for (int item = blockIdx.x; item < NITEMS; item += NCTAS) {
        const int bp   = item >> 6;          // batch pair
        const int tile = item & 63;
        const int q0 = (tile & 7) * TPQ;
        const int p0 = (tile >> 3) * TPP;
        const float q0f = (float)q0, p0f = (float)p0;

        // ---- load endpoints for both batches (threads 0..127) ----
        if (t < 128) {
            const int bb = t >> 6;
            const int k  = t & 63;
            const int b  = bp * 2 + bb;
            float X, Y;
            if (k < 32) {
                X = iv00[(b * 32 + k) * 2 + 0] * INV_SIDE;
                Y = iv00[(b * 32 + k) * 2 + 1] * INV_SIDE;
            } else {
                X = iv01[(b * 32 + (k - 32)) * 2 + 1] * INV_SIDE - 512.0f;
                Y = iv01[(b * 32 + (k - 32)) * 2 + 0] * INV_SIDE;
            }
            Xs[t] = X;
            Ys[t] = Y;
        }
        __syncthreads();

        #pragma unroll 1
        for (int u = 0; u < 4; ++u) {
            const int bb  = u >> 1;
            const int img = u & 1;
            const int ko  = bb * 64;         // offset into Xs/Ys

            // ---- classification (threads 0..63; k>=32 inactive for img1) ----
            int cls = 0;         // 0 skip, 1 both-one, 2 A(h==1), 3 B(u==1), 4 C
            int myPrefix = 0;
            if (t < 64) {
                const bool active = (img == 0) || (t < 32);
                if (active) {
                    const float X = Xs[ko + t], Y = Ys[ko + t];
                    bool hz, ho, uz, uo;
                    if (img == 0) {
                        hz = (Y <= q0f) || (q0f + (TPQ - 1.0f) <= X - 1.0f);
                        ho = (X <= q0f) && (Y >= q0f + (float)TPQ);
                        uz = (p0f >= 512.0f - Y) || (p0f + (TPP - 1.0f) <= -X - 1.0f);
                        uo = (p0f >= -X) && (p0f + (TPP - 1.0f) <= 511.0f - Y);
                    } else {
                        hz = (q0f + (TPQ - 1.0f) <= X - 1.0f);
                        ho = (X <= q0f);
                        uz = (p0f + (TPP - 1.0f) <= 511.0f - Y);
                        uo = (p0f >= 512.0f - Y);
                    }
                    if (!(hz || uz)) {
                        if (ho && uo) cls = 1;
                        else if (ho) cls = 2;
                        else if (uo) cls = 3;
                        else cls = 4;
                    }
                }
                const unsigned full = 0xFFFFFFFFu;
                unsigned m1 = __ballot_sync(full, cls == 1);
                unsigned mA = __ballot_sync(full, cls == 2);
                unsigned mB = __ballot_sync(full, cls == 3);
                unsigned mC = __ballot_sync(full, cls == 4);
                int w = t >> 5;
                if ((t & 31) == 0) {
                    wCnt[w][0] = __popc(m1); wCnt[w][1] = __popc(mA);
                    wCnt[w][2] = __popc(mB); wCnt[w][3] = __popc(mC);
                }
                unsigned lt = (1u << (t & 31)) - 1u;
                if (cls == 2) myPrefix = __popc(mA & lt);
                else if (cls == 3) myPrefix = __popc(mB & lt);
                else if (cls == 4) myPrefix = __popc(mC & lt);
            }
            __syncthreads();

            const int nA = wCnt[0][1] + wCnt[1][1];
            const int nB = wCnt[0][2] + wCnt[1][2];
            const int nC = wCnt[0][3] + wCnt[1][3];
            const float c0 = (float)(wCnt[0][0] + wCnt[1][0]);

            if (t < 64 && cls >= 2) {
                int w = t >> 5;
                int base = (w == 1) ? wCnt[0][cls - 1] : 0;
                int pos = base + myPrefix;
                if (cls == 2) listA[pos] = (unsigned char)t;
                else if (cls == 3) listB[pos] = (unsigned char)t;
                else listC[pos] = (unsigned char)t;
            }
            __syncthreads();

            // ---- fused: separable sums (t<128) || chunk-0 factor gen ----
            const int cn0 = min(CH, nC);
            if (t < TPP) {
                float fp = (float)(p0 + t);
                float s = 0.0f;
                for (int i = 0; i < nA; ++i) {
                    int k = ko + listA[i];
                    s += u_of(img, Xs[k], Ys[k], fp);
                }
                Arow[t] = s;
            } else if (t < TPP + TPQ) {
                float fq = (float)(q0 + (t - TPP));
                float s = 0.0f;
                for (int i = 0; i < nB; ++i) {
                    int k = ko + listB[i];
                    s += h_of(img, Xs[k], Ys[k], fq);
                }
                Bcol[t - TPP] = s;
            } else {
                for (int idx = t - 128; idx < cn0 * TPP; idx += 128) {
                    int kk = idx >> 6;                // TPP == 64
                    int j  = idx & (TPP - 1);
                    int k  = ko + listC[kk];
                    float X = Xs[k], Y = Ys[k];
                    float fj = (float)j;
                    Us[kk][j] = u_of(img, X, Y, p0f + fj);
                    Hs[kk][j] = h_of(img, X, Y, q0f + fj);
                }
            }
            __syncthreads();

            float acc[4][4];
            #pragma unroll
            for (int i = 0; i < 4; ++i)
                #pragma unroll
                for (int j = 0; j < 4; ++j)
                    acc[i][j] = 0.0f;

            for (int cb = 0; cb < nC; cb += CH) {
                const int cn = min(CH, nC - cb);
                if (cb) {
                    __syncthreads();              // protect Us/Hs reuse
                    for (int idx = t; idx < cn * TPP; idx += NTHREADS) {
                        int kk = idx >> 6;        // TPP == 64
                        int j  = idx & (TPP - 1);
                        int k  = ko + listC[cb + kk];
                        float X = Xs[k], Y = Ys[k];
                        float fj = (float)j;
                        Us[kk][j] = u_of(img, X, Y, p0f + fj);
                        Hs[kk][j] = h_of(img, X, Y, q0f + fj);
                    }
                    __syncthreads();
                }

                #pragma unroll 4
                for (int kk = 0; kk < cn; ++kk) {
                    float4 u0 = *reinterpret_cast<const float4*>(&Us[kk][ty * 4]);
                    float4 h0 = *reinterpret_cast<const float4*>(&Hs[kk][tx * 4]);
                    float uu[4] = {u0.x, u0.y, u0.z, u0.w};
                    float hh[4] = {h0.x, h0.y, h0.z, h0.w};
                    #pragma unroll
                    for (int i = 0; i < 4; ++i)
                        #pragma unroll
                        for (int j = 0; j < 4; ++j)
                            acc[i][j] = fmaf(uu[i], hh[j], acc[i][j]);
                }
            }

            // ---- combine and store (streaming); no trailing barrier ----
            float4 bv = *reinterpret_cast<const float4*>(&Bcol[tx * 4]);
            const size_t base = ((size_t)((bp * 2 + bb) * 2 + img)) * PDIM * PDIM;
            #pragma unroll
            for (int i = 0; i < 4; ++i) {
                int ri = ty * 4 + i;
                float a = c0 + Arow[ri];
                float* row = out + base + (size_t)(p0 + ri) * PDIM + q0;
                stcs4(row + tx * 4,
                      make_float4(acc[i][0] + a + bv.x, acc[i][1] + a + bv.y,
                                  acc[i][2] + a + bv.z, acc[i][3] + a + bv.w));
            }
        }
        __syncthreads();   // Xs/Ys rewrite fence for next item
    }
}

extern "C" void kernel_launch(void* const* d_in, const int* in_sizes, int n_in,
                              void* d_out, int out_size)
{
    const float* iv00 = (const float*)d_in[0];   // intervals00 (256,32,2)
    const float* iv01 = (const float*)d_in[1];   // intervals01 (256,32,2)
    float* out = (float*)d_out;                  // (256,2,512,512) fp32

    hilbert_raster_kernel<<<NCTAS, NTHREADS>>>(iv00, iv01, out);
}

// round 16
// speedup vs baseline: 1.1593x; 1.1593x over previous
#include <cuda_runtime.h>

#define PDIM     512
#define TPQ      64
#define TPP      64
#define CH       16
#define NTHREADS 256

__device__ __forceinline__ float clamp01f(float v) {
    return fminf(fmaxf(v, 0.0f), 1.0f);
}

__device__ __forceinline__ float h_of(int img, float X, float Y, float fq) {
    return (img == 0) ? clamp01f(fminf(fq + 1.0f - X, Y - fq))
                      : clamp01f(fq + 1.0f - X);
}
__device__ __forceinline__ float u_of(int img, float X, float Y, float fp) {
    return (img == 0) ? clamp01f(fminf(512.0f - fp - Y, X + 1.0f + fp))
                      : clamp01f(Y - 511.0f + fp);
}

__device__ __forceinline__ void stcs4(float* p, float4 v) {
    asm volatile("st.global.cs.v4.f32 [%0], {%1,%2,%3,%4};"
                 :: "l"(p), "f"(v.x), "f"(v.y), "f"(v.z), "f"(v.w) : "memory");
}

__global__ __launch_bounds__(NTHREADS, 6)
void hilbert_raster_kernel(const float* __restrict__ iv00,
                           const float* __restrict__ iv01,
                           float* __restrict__ out)
{
    __shared__ float Xs[128], Ys[128];            // two batches of 64 factors
    __shared__ float Arow[TPP], Bcol[TPQ];
    __shared__ unsigned char listA[4][64], listB[4][64], listC[4][64];
    __shared__ int wCnt[8][4];                    // per-warp class counts
    __shared__ float Us[CH][TPP], Hs[CH][TPQ];

    const int t  = threadIdx.x;
    const int bp = blockIdx.z;           // batch pair: batches 2*bp, 2*bp+1
    const int q0 = blockIdx.x * TPQ;
    const int p0 = blockIdx.y * TPP;
    const float q0f = (float)q0, p0f = (float)p0;
    const float INV_SIDE = 325.94932345220167f;  // 1024/pi

    // ---- load endpoints for both batches (threads 0..127) ----
    if (t < 128) {
        const int bb = t >> 6;
        const int k  = t & 63;
        const int b  = bp * 2 + bb;
        float X, Y;
        if (k < 32) {
            X = iv00[(b * 32 + k) * 2 + 0] * INV_SIDE;
            Y = iv00[(b * 32 + k) * 2 + 1] * INV_SIDE;
        } else {
            X = iv01[(b * 32 + (k - 32)) * 2 + 1] * INV_SIDE - 512.0f;
            Y = iv01[(b * 32 + (k - 32)) * 2 + 0] * INV_SIDE;
        }
        Xs[t] = X;
        Ys[t] = Y;
    }
    __syncthreads();

    // ---- one-pass classification: thread t handles (unit u, factor k) ----
    // unit u = bb*2+img covers warps 2u, 2u+1 exactly.
    int cls = 0;                 // 0 skip, 1 both-one, 2 A(h==1), 3 B(u==1), 4 C
    int myPrefix = 0;
    const int cu  = t >> 6;              // this thread's classification unit
    const int ck  = t & 63;
    {
        const int cbb  = cu >> 1;
        const int cimg = cu & 1;
        const bool active = (cimg == 0) || (ck < 32);
        if (active) {
            const float X = Xs[cbb * 64 + ck], Y = Ys[cbb * 64 + ck];
            bool hz, ho, uz, uo;
            if (cimg == 0) {
                hz = (Y <= q0f) || (q0f + (TPQ - 1.0f) <= X - 1.0f);
                ho = (X <= q0f) && (Y >= q0f + (float)TPQ);
                uz = (p0f >= 512.0f - Y) || (p0f + (TPP - 1.0f) <= -X - 1.0f);
                uo = (p0f >= -X) && (p0f + (TPP - 1.0f) <= 511.0f - Y);
            } else {
                hz = (q0f + (TPQ - 1.0f) <= X - 1.0f);
                ho = (X <= q0f);
                uz = (p0f + (TPP - 1.0f) <= 511.0f - Y);
                uo = (p0f >= 512.0f - Y);
            }
            if (!(hz || uz)) {
                if (ho && uo) cls = 1;
                else if (ho) cls = 2;
                else if (uo) cls = 3;
                else cls = 4;
            }
        }
        const unsigned full = 0xFFFFFFFFu;
        unsigned m1 = __ballot_sync(full, cls == 1);
        unsigned mA = __ballot_sync(full, cls == 2);
        unsigned mB = __ballot_sync(full, cls == 3);
        unsigned mC = __ballot_sync(full, cls == 4);
        int w = t >> 5;
        if ((t & 31) == 0) {
            wCnt[w][0] = __popc(m1); wCnt[w][1] = __popc(mA);
            wCnt[w][2] = __popc(mB); wCnt[w][3] = __popc(mC);
        }
        unsigned lt = (1u << (t & 31)) - 1u;
        if (cls == 2) myPrefix = __popc(mA & lt);
        else if (cls == 3) myPrefix = __popc(mB & lt);
        else if (cls == 4) myPrefix = __popc(mC & lt);
    }
    __syncthreads();

    if (cls >= 2) {
        const int wInU = (t >> 5) & 1;               // warp within unit
        const int base = wInU ? wCnt[cu * 2][cls - 1] : 0;
        const int pos  = base + myPrefix;
        if (cls == 2) listA[cu][pos] = (unsigned char)ck;
        else if (cls == 3) listB[cu][pos] = (unsigned char)ck;
        else listC[cu][pos] = (unsigned char)ck;
    }
    __syncthreads();

    const int tx = t & 15;   // q: 16 groups * 4 cols = 64
    const int ty = t >> 4;   // p: 16 groups * 4 rows = 64

    #pragma unroll 1
    for (int u = 0; u < 4; ++u) {
        const int bb  = u >> 1;
        const int img = u & 1;
        const int ko  = bb * 64;         // offset into Xs/Ys

        const int nA = wCnt[u * 2][1] + wCnt[u * 2 + 1][1];
        const int nB = wCnt[u * 2][2] + wCnt[u * 2 + 1][2];
        const int nC = wCnt[u * 2][3] + wCnt[u * 2 + 1][3];
        const float c0 = (float)(wCnt[u * 2][0] + wCnt[u * 2 + 1][0]);

        // ---- fused: separable sums (t<128) || chunk-0 factor gen ----
        const int cn0 = min(CH, nC);
        if (t < TPP) {
            float fp = (float)(p0 + t);
            float s = 0.0f;
            for (int i = 0; i < nA; ++i) {
                int k = ko + listA[u][i];
                s += u_of(img, Xs[k], Ys[k], fp);
            }
            Arow[t] = s;
        } else if (t < TPP + TPQ) {
            float fq = (float)(q0 + (t - TPP));
            float s = 0.0f;
            for (int i = 0; i < nB; ++i) {
                int k = ko + listB[u][i];
                s += h_of(img, Xs[k], Ys[k], fq);
            }
            Bcol[t - TPP] = s;
        } else {
            for (int idx = t - 128; idx < cn0 * TPP; idx += 128) {
                int kk = idx >> 6;                // TPP == 64
                int j  = idx & (TPP - 1);
                int k  = ko + listC[u][kk];
                float X = Xs[k], Y = Ys[k];
                float fj = (float)j;
                Us[kk][j] = u_of(img, X, Y, p0f + fj);
                Hs[kk][j] = h_of(img, X, Y, q0f + fj);
            }
        }
        __syncthreads();

        float acc[4][4];
        #pragma unroll
        for (int i = 0; i < 4; ++i)
            #pragma unroll
            for (int j = 0; j < 4; ++j)
                acc[i][j] = 0.0f;

        for (int cb = 0; cb < nC; cb += CH) {
            const int cn = min(CH, nC - cb);
            if (cb) {
                __syncthreads();              // protect Us/Hs reuse
                for (int idx = t; idx < cn * TPP; idx += NTHREADS) {
                    int kk = idx >> 6;        // TPP == 64
                    int j  = idx & (TPP - 1);
                    int k  = ko + listC[u][cb + kk];
                    float X = Xs[k], Y = Ys[k];
                    float fj = (float)j;
                    Us[kk][j] = u_of(img, X, Y, p0f + fj);
                    Hs[kk][j] = h_of(img, X, Y, q0f + fj);
                }
                __syncthreads();
            }

            #pragma unroll 4
            for (int kk = 0; kk < cn; ++kk) {
                float4 u0 = *reinterpret_cast<const float4*>(&Us[kk][ty * 4]);
                float4 h0 = *reinterpret_cast<const float4*>(&Hs[kk][tx * 4]);
                float uu[4] = {u0.x, u0.y, u0.z, u0.w};
                float hh[4] = {h0.x, h0.y, h0.z, h0.w};
                #pragma unroll
                for (int i = 0; i < 4; ++i)
                    #pragma unroll
                    for (int j = 0; j < 4; ++j)
                        acc[i][j] = fmaf(uu[i], hh[j], acc[i][j]);
            }
        }

        // ---- combine and store (streaming) ----
        float4 bv = *reinterpret_cast<const float4*>(&Bcol[tx * 4]);
        const size_t base = ((size_t)((bp * 2 + bb) * 2 + img)) * PDIM * PDIM;
        #pragma unroll
        for (int i = 0; i < 4; ++i) {
            int ri = ty * 4 + i;
            float a = c0 + Arow[ri];
            float* row = out + base + (size_t)(p0 + ri) * PDIM + q0;
            stcs4(row + tx * 4,
                  make_float4(acc[i][0] + a + bv.x, acc[i][1] + a + bv.y,
                              acc[i][2] + a + bv.z, acc[i][3] + a + bv.w));
        }

        // fence Arow/Bcol/Us/Hs reuse by the next unit (skip after last)
        if (u < 3) __syncthreads();
    }
}

extern "C" void kernel_launch(void* const* d_in, const int* in_sizes, int n_in,
                              void* d_out, int out_size)
{
    const float* iv00 = (const float*)d_in[0];   // intervals00 (256,32,2)
    const float* iv01 = (const float*)d_in[1];   // intervals01 (256,32,2)
    float* out = (float*)d_out;                  // (256,2,512,512) fp32

    dim3 grid(PDIM / TPQ, PDIM / TPP, 128);      // z = batch pair
    hilbert_raster_kernel<<<grid, NTHREADS>>>(iv00, iv01, out);
}